// round 16
// baseline (speedup 1.0000x reference)
#include <cuda_runtime.h>
#include <cuda_fp16.h>
#include <float.h>
#include <cstdint>

#define ALPHA 0.2f

// ---------------- static device scratch (no runtime allocation) ----------------
__device__ __align__(16) __half g_Whi[256 * 512];           // W hi fp16 [OUT_F, IN_F]
__device__ __align__(16) __half g_Wlo[256 * 512];           // W lo
__device__ __align__(16) __half g_WhT[256 * 8192];          // Wh^T fp16 [OUT_F, N]
__device__ __align__(16) __half g_attn_h[8192ull * 8192];   // attention fp16
__device__ __align__(16) float g_spart[8 * 8192];           // s partials [8 groups][N]
__device__ __align__(16) float g_ssrc[8192];
__device__ __align__(16) float g_sdst[8192];
__device__ __align__(16) float g_attn_fb[67108864];         // fallback fp32 attention

// ==================== PTX helpers (portable sm_80+ subset) ====================
__device__ __forceinline__ uint32_t smem_u32(const void* p) {
    uint32_t a;
    asm("{ .reg .u64 t; cvta.to.shared.u64 t, %1; cvt.u32.u64 %0, t; }" : "=r"(a) : "l"(p));
    return a;
}
__device__ __forceinline__ void cp16(uint32_t dst, const void* src) {
    asm volatile("cp.async.cg.shared.global [%0], [%1], 16;" :: "r"(dst), "l"(src) : "memory");
}
__device__ __forceinline__ void cp_commit() {
    asm volatile("cp.async.commit_group;" ::: "memory");
}
template <int Ngrp>
__device__ __forceinline__ void cp_wait() {
    asm volatile("cp.async.wait_group %0;" :: "n"(Ngrp) : "memory");
}
__device__ __forceinline__ void ldsm_x4(uint32_t* r, uint32_t addr) {
    asm volatile("ldmatrix.sync.aligned.m8n8.x4.shared.b16 {%0,%1,%2,%3}, [%4];"
                 : "=r"(r[0]), "=r"(r[1]), "=r"(r[2]), "=r"(r[3]) : "r"(addr));
}
__device__ __forceinline__ void mma16816(float* c, const uint32_t* a, const uint32_t* b) {
    asm volatile("mma.sync.aligned.m16n8k16.row.col.f32.f16.f16.f32 "
                 "{%0,%1,%2,%3}, {%4,%5,%6,%7}, {%8,%9}, {%0,%1,%2,%3};"
                 : "+f"(c[0]), "+f"(c[1]), "+f"(c[2]), "+f"(c[3])
                 : "r"(a[0]), "r"(a[1]), "r"(a[2]), "r"(a[3]), "r"(b[0]), "r"(b[1]));
}
__device__ __forceinline__ void sts_v2(uint32_t addr, uint32_t x, uint32_t y) {
    asm volatile("st.shared.v2.b32 [%0], {%1,%2};" :: "r"(addr), "r"(x), "r"(y) : "memory");
}
__device__ __forceinline__ void lds_v4(uint32_t addr, uint32_t* u) {
    asm volatile("ld.shared.v4.b32 {%0,%1,%2,%3}, [%4];"
                 : "=r"(u[0]), "=r"(u[1]), "=r"(u[2]), "=r"(u[3]) : "r"(addr));
}
__device__ __forceinline__ uint32_t split2(float x, float y, uint32_t& lo) {
    __half hx = __float2half_rn(x);
    __half hy = __float2half_rn(y);
    __half lx = __float2half_rn(x - __half2float(hx));
    __half ly = __float2half_rn(y - __half2float(hy));
    lo = (uint32_t)__half_as_ushort(lx) | ((uint32_t)__half_as_ushort(ly) << 16);
    return (uint32_t)__half_as_ushort(hx) | ((uint32_t)__half_as_ushort(hy) << 16);
}

#define ROWB   80                                // 32 fp16 (64B) + 16B skew
#define TILEB  (128 * ROWB)                      // 10240 B

// ==================== GEMM-1 fused (identical to R8) ====================
#define G1_DSMEM (4 * 2 * TILEB + 2 * 2 * TILEB)  // 122880

__global__ __launch_bounds__(256, 1)
void gemm1_fused(const float* __restrict__ A, const __half* __restrict__ Bhi,
                 const __half* __restrict__ Blo, __half* __restrict__ WhT,
                 float* __restrict__ spart, const float* __restrict__ a_vec,
                 int K, int niter, int M, int OUTF) {
    extern __shared__ __align__(128) char dsm[];
    const uint32_t sb = smem_u32(dsm);

    const int tid   = threadIdx.x;
    const int wid   = tid >> 5;
    const int lane  = tid & 31;
    const int warpM = wid & 3;
    const int warpN = wid >> 2;
    const int mBase = blockIdx.x * 128;
    const int colBase = blockIdx.y * 128;

    float acc[2][8][4];
#pragma unroll
    for (int mt = 0; mt < 2; mt++)
#pragma unroll
        for (int nt = 0; nt < 8; nt++)
#pragma unroll
            for (int q = 0; q < 4; q++) acc[mt][nt][q] = 0.0f;

    float4 areg[4];

    auto Bst = [&](int s) { return sb + s * (2 * TILEB); };
    auto Ast = [&](int s) { return sb + 4 * 2 * TILEB + s * (2 * TILEB); };

    auto loadB = [&](int s, int it) {
#pragma unroll
        for (int t = 0; t < 4; t++) {
            const int c = tid + t * 256;
            const int tile = c >> 9;
            const int r = (c >> 2) & 127;
            const int seg = c & 3;
            cp16(Bst(s) + tile * TILEB + r * ROWB + seg * 16,
                 (tile ? Blo : Bhi) + (size_t)(colBase + r) * K + it * 32 + seg * 8);
        }
    };
    auto ldgA = [&](int it) {
#pragma unroll
        for (int t = 0; t < 4; t++) {
            const int c = tid + t * 256;
            const int row = c >> 3;
            const int seg = c & 7;
            areg[t] = *(const float4*)(A + (size_t)(mBase + row) * K + it * 32 + seg * 4);
        }
    };
    auto stsA = [&](int s) {
        const uint32_t ahi = Ast(s);
        const uint32_t alo = ahi + TILEB;
#pragma unroll
        for (int t = 0; t < 4; t++) {
            const int c = tid + t * 256;
            const int row = c >> 3;
            const int seg = c & 7;
            const uint32_t off = row * ROWB + seg * 8;
            uint32_t l0, l1;
            uint32_t h0 = split2(areg[t].x, areg[t].y, l0);
            uint32_t h1 = split2(areg[t].z, areg[t].w, l1);
            sts_v2(ahi + off, h0, h1);
            sts_v2(alo + off, l0, l1);
        }
    };

    const uint32_t a_off = (uint32_t)(warpM * 32 + (lane & 15)) * ROWB + (lane >> 4) * 16;
    const uint32_t b_off = (uint32_t)(warpN * 64 + ((lane >> 4) & 1) * 8 + (lane & 7)) * ROWB
                         + ((lane >> 3) & 1) * 16;

    auto compute = [&](int sB, int sA) {
        const uint32_t ahi = Ast(sA);
        const uint32_t alo = ahi + TILEB;
        const uint32_t bhi = Bst(sB);
        const uint32_t blo = bhi + TILEB;
#pragma unroll
        for (int ks = 0; ks < 2; ks++) {
            uint32_t ah[2][4], al[2][4];
            ldsm_x4(ah[0], ahi + a_off + ks * 32);
            ldsm_x4(ah[1], ahi + a_off + 16 * ROWB + ks * 32);
            ldsm_x4(al[0], alo + a_off + ks * 32);
            ldsm_x4(al[1], alo + a_off + 16 * ROWB + ks * 32);
#pragma unroll
            for (int p = 0; p < 4; p++) {
                uint32_t bh[4], bl[4];
                ldsm_x4(bh, bhi + b_off + p * 16 * ROWB + ks * 32);
                ldsm_x4(bl, blo + b_off + p * 16 * ROWB + ks * 32);
#pragma unroll
                for (int mt = 0; mt < 2; mt++) {
                    mma16816(acc[mt][2 * p],     ah[mt], bh + 0);
                    mma16816(acc[mt][2 * p + 1], ah[mt], bh + 2);
                    mma16816(acc[mt][2 * p],     ah[mt], bl + 0);
                    mma16816(acc[mt][2 * p + 1], ah[mt], bl + 2);
                    mma16816(acc[mt][2 * p],     al[mt], bh + 0);
                    mma16816(acc[mt][2 * p + 1], al[mt], bh + 2);
                }
            }
        }
    };

    ldgA(0);
    loadB(0, 0); cp_commit();
    if (niter > 1) loadB(1, 1);
    cp_commit();
    if (niter > 2) loadB(2, 2);
    cp_commit();
    stsA(0);

    for (int it = 0; it < niter; it++) {
        cp_wait<2>();
        __syncthreads();
        if (it + 3 < niter) loadB((it + 3) & 3, it + 3);
        cp_commit();
        if (it + 1 < niter) ldgA(it + 1);
        compute(it & 3, it & 1);
        if (it + 1 < niter) stsA((it + 1) & 1);
        __syncthreads();
    }

    // epilogue 1: s partials from fp32 acc
    {
        float a1v[16], a2v[16];
#pragma unroll
        for (int nt = 0; nt < 8; nt++)
#pragma unroll
            for (int e = 0; e < 2; e++) {
                const int col = colBase + warpN * 64 + nt * 8 + (lane & 3) * 2 + e;
                a1v[nt * 2 + e] = a_vec[col];
                a2v[nt * 2 + e] = a_vec[OUTF + col];
            }
        const int g = (blockIdx.y << 1) | warpN;
#pragma unroll
        for (int mt = 0; mt < 2; mt++)
#pragma unroll
            for (int half = 0; half < 2; half++) {
                float p1 = 0.0f, p2 = 0.0f;
#pragma unroll
                for (int nt = 0; nt < 8; nt++)
#pragma unroll
                    for (int e = 0; e < 2; e++) {
                        const float v = acc[mt][nt][half * 2 + e];
                        p1 += v * a1v[nt * 2 + e];
                        p2 += v * a2v[nt * 2 + e];
                    }
                p1 += __shfl_xor_sync(0xffffffffu, p1, 1);
                p1 += __shfl_xor_sync(0xffffffffu, p1, 2);
                p2 += __shfl_xor_sync(0xffffffffu, p2, 1);
                p2 += __shfl_xor_sync(0xffffffffu, p2, 2);
                if ((lane & 3) == 0) {
                    const int row = mBase + warpM * 32 + mt * 16 + (lane >> 2) + half * 8;
                    spart[g * M + row] = p1;
                    spart[(g + 4) * M + row] = p2;
                }
            }
    }

    // epilogue 2: WhT fp16 transposed via smem
    {
        __half* sT = (__half*)dsm;
        __syncthreads();
#pragma unroll
        for (int mt = 0; mt < 2; mt++)
#pragma unroll
            for (int nt = 0; nt < 8; nt++)
#pragma unroll
                for (int q = 0; q < 4; q++) {
                    const int nl = warpN * 64 + nt * 8 + (lane & 3) * 2 + (q & 1);
                    const int ml = warpM * 32 + mt * 16 + (lane >> 2) + (q >> 1) * 8;
                    sT[nl * 136 + ml] = __float2half_rn(acc[mt][nt][q]);
                }
        __syncthreads();
#pragma unroll
        for (int t = 0; t < 8; t++) {
            const int c = tid + t * 256;
            const int n = c >> 4;
            const int m8 = (c & 15) * 8;
            uint4 v = *(const uint4*)&sT[n * 136 + m8];
            *(uint4*)&WhT[(size_t)(colBase + n) * M + mBase + m8] = v;
        }
    }
}

// ---------------- combine s partials ----------------
__global__ void combine_s(const float* __restrict__ spart, float* __restrict__ ssrc,
                          float* __restrict__ sdst, int M) {
    int i = blockIdx.x * blockDim.x + threadIdx.x;
    if (i >= M) return;
    ssrc[i] = spart[0 * M + i] + spart[1 * M + i] + spart[2 * M + i] + spart[3 * M + i];
    sdst[i] = spart[4 * M + i] + spart[5 * M + i] + spart[6 * M + i] + spart[7 * M + i];
}

// ==================== GEMM-2 (R8 shape) + alternating streaming attention store ====================
// A = attention fp16, B = WhT fp16, 8-stage cp.async, single product, 128 CTAs.
// Every CTA stores fp32 attention for its A tile when (it & 1) == blockIdx.y.
// Stores use st.global.cs (evict-first) to keep WhT / prefetch window in L2.
#define G2_NSTAGE 8
#define G2_DSMEM  (G2_NSTAGE * 2 * TILEB)        // 163840

__global__ __launch_bounds__(256, 1)
void mma_gemm2(const __half* __restrict__ Ah, const __half* __restrict__ Bh,
               float* __restrict__ attn, float* __restrict__ C, int K, int niter) {
    extern __shared__ __align__(128) char dsm[];
    const uint32_t sb = smem_u32(dsm);

    const int tid   = threadIdx.x;
    const int wid   = tid >> 5;
    const int lane  = tid & 31;
    const int warpM = wid & 3;
    const int warpN = wid >> 2;
    const int mBase = blockIdx.x * 128;
    const int colBase = blockIdx.y * 128;
    const int storePar = blockIdx.y & 1;

    float acc[2][8][4];
#pragma unroll
    for (int mt = 0; mt < 2; mt++)
#pragma unroll
        for (int nt = 0; nt < 8; nt++)
#pragma unroll
            for (int q = 0; q < 4; q++) acc[mt][nt][q] = 0.0f;

    auto loadStage = [&](int s, int it) {
        const uint32_t st = sb + s * (2 * TILEB);
#pragma unroll
        for (int t = 0; t < 4; t++) {
            const int c = tid + t * 256;
            const int tile = c >> 9;              // 0:A 1:B
            const int r = (c >> 2) & 127;
            const int seg = c & 3;
            const __half* base = tile ? Bh : Ah;
            const int rowg = tile ? (colBase + r) : (mBase + r);
            cp16(st + tile * TILEB + r * ROWB + seg * 16,
                 base + (size_t)rowg * K + it * 32 + seg * 8);
        }
    };

    // fp32 attention store (streaming) from the resident A fp16 tile
    auto storeAttn = [&](int s, int it) {
        const uint32_t ast = sb + s * (2 * TILEB);
#pragma unroll
        for (int t = 0; t < 2; t++) {
            const int c = tid + t * 256;          // 512 chunks of 8 halfs
            const int r = c >> 2;
            const int seg = c & 3;
            uint32_t u[4];
            lds_v4(ast + r * ROWB + seg * 16, u);
            float* dst = attn + (size_t)(mBase + r) * K + it * 32 + seg * 8;
            float2 f0 = __half22float2(*(__half2*)&u[0]);
            float2 f1 = __half22float2(*(__half2*)&u[1]);
            float2 f2 = __half22float2(*(__half2*)&u[2]);
            float2 f3 = __half22float2(*(__half2*)&u[3]);
            __stcs((float4*)dst,       make_float4(f0.x, f0.y, f1.x, f1.y));
            __stcs((float4*)(dst + 4), make_float4(f2.x, f2.y, f3.x, f3.y));
        }
    };

    const uint32_t a_off = (uint32_t)(warpM * 32 + (lane & 15)) * ROWB + (lane >> 4) * 16;
    const uint32_t b_off = (uint32_t)(warpN * 64 + ((lane >> 4) & 1) * 8 + (lane & 7)) * ROWB
                         + ((lane >> 3) & 1) * 16;

    auto compute = [&](int s) {
        const uint32_t ahi = sb + s * (2 * TILEB);
        const uint32_t bhi = ahi + TILEB;
#pragma unroll
        for (int ks = 0; ks < 2; ks++) {
            uint32_t ah[2][4];
            ldsm_x4(ah[0], ahi + a_off + ks * 32);
            ldsm_x4(ah[1], ahi + a_off + 16 * ROWB + ks * 32);
#pragma unroll
            for (int p = 0; p < 4; p++) {
                uint32_t bh[4];
                ldsm_x4(bh, bhi + b_off + p * 16 * ROWB + ks * 32);
#pragma unroll
                for (int mt = 0; mt < 2; mt++) {
                    mma16816(acc[mt][2 * p],     ah[mt], bh + 0);
                    mma16816(acc[mt][2 * p + 1], ah[mt], bh + 2);
                }
            }
        }
    };

#pragma unroll
    for (int s = 0; s < G2_NSTAGE - 1; s++) {
        if (s < niter) loadStage(s, s);
        cp_commit();
    }
    for (int it = 0; it < niter; it++) {
        cp_wait<G2_NSTAGE - 2>();
        __syncthreads();
        if (it + G2_NSTAGE - 1 < niter)
            loadStage((it + G2_NSTAGE - 1) & (G2_NSTAGE - 1), it + G2_NSTAGE - 1);
        cp_commit();
        if ((it & 1) == storePar) storeAttn(it & (G2_NSTAGE - 1), it);
        compute(it & (G2_NSTAGE - 1));
    }

#pragma unroll
    for (int mt = 0; mt < 2; mt++) {
        const int r0 = mBase + warpM * 32 + mt * 16 + (lane >> 2);
#pragma unroll
        for (int nt = 0; nt < 8; nt++) {
            const int col = colBase + warpN * 64 + nt * 8 + (lane & 3) * 2;
            *(float2*)(C + (size_t)r0 * 256 + col) = make_float2(acc[mt][nt][0], acc[mt][nt][1]);
            *(float2*)(C + (size_t)(r0 + 8) * 256 + col) = make_float2(acc[mt][nt][2], acc[mt][nt][3]);
        }
    }
}

// ---------------- prep: W fp32 -> fp16 hi/lo ----------------
__global__ void prep_split(const float* __restrict__ X, __half* __restrict__ hi,
                           __half* __restrict__ lo, int n4) {
    int i = blockIdx.x * blockDim.x + threadIdx.x;
    if (i >= n4) return;
    float4 v = ((const float4*)X)[i];
    __half h0 = __float2half_rn(v.x), h1 = __float2half_rn(v.y);
    __half h2 = __float2half_rn(v.z), h3 = __float2half_rn(v.w);
    __half l0 = __float2half_rn(v.x - __half2float(h0));
    __half l1 = __float2half_rn(v.y - __half2float(h1));
    __half l2 = __float2half_rn(v.z - __half2float(h2));
    __half l3 = __float2half_rn(v.w - __half2float(h3));
    ((uint2*)hi)[i] = make_uint2(
        (uint32_t)__half_as_ushort(h0) | ((uint32_t)__half_as_ushort(h1) << 16),
        (uint32_t)__half_as_ushort(h2) | ((uint32_t)__half_as_ushort(h3) << 16));
    ((uint2*)lo)[i] = make_uint2(
        (uint32_t)__half_as_ushort(l0) | ((uint32_t)__half_as_ushort(l1) << 16),
        (uint32_t)__half_as_ushort(l2) | ((uint32_t)__half_as_ushort(l3) << 16));
}

// ---------------- masked row softmax (2-pass, fp16 output only) ----------------
__global__ __launch_bounds__(512)
void attn_softmax(const float* __restrict__ adj, const float* __restrict__ sdst,
                  const float* __restrict__ ssrc, __half* __restrict__ atth, int Nn) {
    extern __shared__ float sh[];
    float* red = sh + Nn;
    const int i = blockIdx.x;
    const int tid = threadIdx.x;
    const int T = blockDim.x;
    const int n4 = Nn >> 2;

    const float4* adj4 = (const float4*)(adj + (size_t)i * Nn);
    const float4* sd4 = (const float4*)sdst;
    float4* sh4 = (float4*)sh;
    const float si = ssrc[i];

    float sum = 0.0f;
    for (int v = tid; v < n4; v += T) {
        float4 a = __ldcs(&adj4[v]);              // streaming read (no reuse)
        float4 s = sd4[v];
        float4 p;
        float x;
        x = si + s.x; x = (x > 0.0f) ? x : ALPHA * x;
        p.x = (a.x > 0.0f) ? __expf(x) : 0.0f;
        x = si + s.y; x = (x > 0.0f) ? x : ALPHA * x;
        p.y = (a.y > 0.0f) ? __expf(x) : 0.0f;
        x = si + s.z; x = (x > 0.0f) ? x : ALPHA * x;
        p.z = (a.z > 0.0f) ? __expf(x) : 0.0f;
        x = si + s.w; x = (x > 0.0f) ? x : ALPHA * x;
        p.w = (a.w > 0.0f) ? __expf(x) : 0.0f;
        sum += p.x + p.y + p.z + p.w;
        sh4[v] = p;
    }
#pragma unroll
    for (int off = 16; off > 0; off >>= 1)
        sum += __shfl_down_sync(0xffffffffu, sum, off);
    if ((tid & 31) == 0) red[tid >> 5] = sum;
    __syncthreads();
    if (tid == 0) {
        float ss = 0.0f;
        int nw = T >> 5;
        for (int w = 0; w < nw; w++) ss += red[w];
        red[32] = ss;
    }
    __syncthreads();
    const float total = red[32];

    uint2* h2 = (uint2*)(atth + (size_t)i * Nn);
    const bool empty = (total == 0.0f);
    const float inv = empty ? (1.0f / (float)Nn) : (1.0f / total);

    for (int v = tid; v < n4; v += T) {
        float4 p;
        if (empty) {
            p = make_float4(inv, inv, inv, inv);  // softmax over all -9e15 = uniform
        } else {
            p = sh4[v];
            p.x *= inv; p.y *= inv; p.z *= inv; p.w *= inv;
        }
        __half q0 = __float2half_rn(p.x), q1 = __float2half_rn(p.y);
        __half q2 = __float2half_rn(p.z), q3 = __float2half_rn(p.w);
        h2[v] = make_uint2(
            (uint32_t)__half_as_ushort(q0) | ((uint32_t)__half_as_ushort(q1) << 16),
            (uint32_t)__half_as_ushort(q2) | ((uint32_t)__half_as_ushort(q3) << 16));
    }
}

// ---------------- launcher ----------------
extern "C" void kernel_launch(void* const* d_in, const int* in_sizes, int n_in,
                              void* d_out, int out_size) {
    const float* h     = (const float*)d_in[0];   // [N, IN_F]
    const float* adj   = (const float*)d_in[1];   // [N, N]
    const float* W     = (const float*)d_in[2];   // [OUT_F, IN_F]
    const float* a_vec = (const float*)d_in[3];   // [2*OUT_F]

    int OUTF = in_sizes[3] / 2;                   // 256
    int INF  = in_sizes[2] / OUTF;                // 512
    int N    = in_sizes[0] / INF;                 // 8192

    float *spart, *ssrc, *sdst, *attn_fb;
    __half *Whi, *Wlo, *WhT, *atth;
    cudaGetSymbolAddress((void**)&Whi,     g_Whi);
    cudaGetSymbolAddress((void**)&Wlo,     g_Wlo);
    cudaGetSymbolAddress((void**)&WhT,     g_WhT);
    cudaGetSymbolAddress((void**)&atth,    g_attn_h);
    cudaGetSymbolAddress((void**)&spart,   g_spart);
    cudaGetSymbolAddress((void**)&ssrc,    g_ssrc);
    cudaGetSymbolAddress((void**)&sdst,    g_sdst);
    cudaGetSymbolAddress((void**)&attn_fb, g_attn_fb);

    float* h_prime = (float*)d_out;
    long long need = (long long)N * OUTF + (long long)N * N;
    float* attn = ((long long)out_size >= need) ? (h_prime + (size_t)N * OUTF) : attn_fb;

    cudaFuncSetAttribute(gemm1_fused, cudaFuncAttributeMaxDynamicSharedMemorySize, G1_DSMEM);
    cudaFuncSetAttribute(mma_gemm2,   cudaFuncAttributeMaxDynamicSharedMemorySize, G2_DSMEM);

    // 1) W -> fp16 hi/lo
    prep_split<<<(OUTF * INF / 4 + 255) / 256, 256>>>(W, Whi, Wlo, OUTF * INF / 4);

    // 2) fused GEMM-1: WhT fp16 + s partials
    gemm1_fused<<<dim3(N / 128, OUTF / 128), 256, G1_DSMEM>>>(
        h, Whi, Wlo, WhT, spart, a_vec, INF, INF / 32, N, OUTF);

    // 3) combine s partials
    combine_s<<<(N + 255) / 256, 256>>>(spart, ssrc, sdst, N);

    // 4) masked softmax -> fp16 attention plane only
    size_t shBytes = (size_t)N * sizeof(float) + 64 * sizeof(float);
    attn_softmax<<<N, 512, shBytes>>>(adj, sdst, ssrc, atth, N);

    // 5) GEMM-2 + alternating streaming fp32 attention store
    mma_gemm2<<<dim3(N / 128, OUTF / 128), 256, G2_DSMEM>>>(atth, WhT, attn, h_prime, N, N / 32);
}

// round 17
// speedup vs baseline: 1.1264x; 1.1264x over previous
#include <cuda_runtime.h>
#include <cuda_fp16.h>
#include <float.h>
#include <cstdint>

#define ALPHA 0.2f

// ---------------- static device scratch (no runtime allocation) ----------------
__device__ __align__(16) __half g_Whi[256 * 512];           // W hi fp16 [OUT_F, IN_F]
__device__ __align__(16) __half g_Wlo[256 * 512];           // W lo
__device__ __align__(16) __half g_WhT[256 * 8192];          // Wh^T fp16 [OUT_F, N]
__device__ __align__(16) __half g_attn_h[8192ull * 8192];   // attention fp16
__device__ __align__(16) float g_spart[8 * 8192];           // s partials [8 groups][N]
__device__ __align__(16) float g_ssrc[8192];
__device__ __align__(16) float g_sdst[8192];
__device__ __align__(16) float g_attn_fb[67108864];         // fallback fp32 attention

// ==================== PTX helpers (portable sm_80+ subset) ====================
__device__ __forceinline__ uint32_t smem_u32(const void* p) {
    uint32_t a;
    asm("{ .reg .u64 t; cvta.to.shared.u64 t, %1; cvt.u32.u64 %0, t; }" : "=r"(a) : "l"(p));
    return a;
}
__device__ __forceinline__ void cp16(uint32_t dst, const void* src) {
    asm volatile("cp.async.cg.shared.global [%0], [%1], 16;" :: "r"(dst), "l"(src) : "memory");
}
__device__ __forceinline__ void cp_commit() {
    asm volatile("cp.async.commit_group;" ::: "memory");
}
template <int Ngrp>
__device__ __forceinline__ void cp_wait() {
    asm volatile("cp.async.wait_group %0;" :: "n"(Ngrp) : "memory");
}
__device__ __forceinline__ void ldsm_x4(uint32_t* r, uint32_t addr) {
    asm volatile("ldmatrix.sync.aligned.m8n8.x4.shared.b16 {%0,%1,%2,%3}, [%4];"
                 : "=r"(r[0]), "=r"(r[1]), "=r"(r[2]), "=r"(r[3]) : "r"(addr));
}
__device__ __forceinline__ void mma16816(float* c, const uint32_t* a, const uint32_t* b) {
    asm volatile("mma.sync.aligned.m16n8k16.row.col.f32.f16.f16.f32 "
                 "{%0,%1,%2,%3}, {%4,%5,%6,%7}, {%8,%9}, {%0,%1,%2,%3};"
                 : "+f"(c[0]), "+f"(c[1]), "+f"(c[2]), "+f"(c[3])
                 : "r"(a[0]), "r"(a[1]), "r"(a[2]), "r"(a[3]), "r"(b[0]), "r"(b[1]));
}
__device__ __forceinline__ void sts_v2(uint32_t addr, uint32_t x, uint32_t y) {
    asm volatile("st.shared.v2.b32 [%0], {%1,%2};" :: "r"(addr), "r"(x), "r"(y) : "memory");
}
__device__ __forceinline__ void lds_v4(uint32_t addr, uint32_t* u) {
    asm volatile("ld.shared.v4.b32 {%0,%1,%2,%3}, [%4];"
                 : "=r"(u[0]), "=r"(u[1]), "=r"(u[2]), "=r"(u[3]) : "r"(addr));
}
__device__ __forceinline__ uint32_t split2(float x, float y, uint32_t& lo) {
    __half hx = __float2half_rn(x);
    __half hy = __float2half_rn(y);
    __half lx = __float2half_rn(x - __half2float(hx));
    __half ly = __float2half_rn(y - __half2float(hy));
    lo = (uint32_t)__half_as_ushort(lx) | ((uint32_t)__half_as_ushort(ly) << 16);
    return (uint32_t)__half_as_ushort(hx) | ((uint32_t)__half_as_ushort(hy) << 16);
}

#define ROWB   80                                // 32 fp16 (64B) + 16B skew
#define TILEB  (128 * ROWB)                      // 10240 B

// ==================== GEMM-1 fused (identical to R8) ====================
#define G1_DSMEM (4 * 2 * TILEB + 2 * 2 * TILEB)  // 122880

__global__ __launch_bounds__(256, 1)
void gemm1_fused(const float* __restrict__ A, const __half* __restrict__ Bhi,
                 const __half* __restrict__ Blo, __half* __restrict__ WhT,
                 float* __restrict__ spart, const float* __restrict__ a_vec,
                 int K, int niter, int M, int OUTF) {
    extern __shared__ __align__(128) char dsm[];
    const uint32_t sb = smem_u32(dsm);

    const int tid   = threadIdx.x;
    const int wid   = tid >> 5;
    const int lane  = tid & 31;
    const int warpM = wid & 3;
    const int warpN = wid >> 2;
    const int mBase = blockIdx.x * 128;
    const int colBase = blockIdx.y * 128;

    float acc[2][8][4];
#pragma unroll
    for (int mt = 0; mt < 2; mt++)
#pragma unroll
        for (int nt = 0; nt < 8; nt++)
#pragma unroll
            for (int q = 0; q < 4; q++) acc[mt][nt][q] = 0.0f;

    float4 areg[4];

    auto Bst = [&](int s) { return sb + s * (2 * TILEB); };
    auto Ast = [&](int s) { return sb + 4 * 2 * TILEB + s * (2 * TILEB); };

    auto loadB = [&](int s, int it) {
#pragma unroll
        for (int t = 0; t < 4; t++) {
            const int c = tid + t * 256;
            const int tile = c >> 9;
            const int r = (c >> 2) & 127;
            const int seg = c & 3;
            cp16(Bst(s) + tile * TILEB + r * ROWB + seg * 16,
                 (tile ? Blo : Bhi) + (size_t)(colBase + r) * K + it * 32 + seg * 8);
        }
    };
    auto ldgA = [&](int it) {
#pragma unroll
        for (int t = 0; t < 4; t++) {
            const int c = tid + t * 256;
            const int row = c >> 3;
            const int seg = c & 7;
            areg[t] = *(const float4*)(A + (size_t)(mBase + row) * K + it * 32 + seg * 4);
        }
    };
    auto stsA = [&](int s) {
        const uint32_t ahi = Ast(s);
        const uint32_t alo = ahi + TILEB;
#pragma unroll
        for (int t = 0; t < 4; t++) {
            const int c = tid + t * 256;
            const int row = c >> 3;
            const int seg = c & 7;
            const uint32_t off = row * ROWB + seg * 8;
            uint32_t l0, l1;
            uint32_t h0 = split2(areg[t].x, areg[t].y, l0);
            uint32_t h1 = split2(areg[t].z, areg[t].w, l1);
            sts_v2(ahi + off, h0, h1);
            sts_v2(alo + off, l0, l1);
        }
    };

    const uint32_t a_off = (uint32_t)(warpM * 32 + (lane & 15)) * ROWB + (lane >> 4) * 16;
    const uint32_t b_off = (uint32_t)(warpN * 64 + ((lane >> 4) & 1) * 8 + (lane & 7)) * ROWB
                         + ((lane >> 3) & 1) * 16;

    auto compute = [&](int sB, int sA) {
        const uint32_t ahi = Ast(sA);
        const uint32_t alo = ahi + TILEB;
        const uint32_t bhi = Bst(sB);
        const uint32_t blo = bhi + TILEB;
#pragma unroll
        for (int ks = 0; ks < 2; ks++) {
            uint32_t ah[2][4], al[2][4];
            ldsm_x4(ah[0], ahi + a_off + ks * 32);
            ldsm_x4(ah[1], ahi + a_off + 16 * ROWB + ks * 32);
            ldsm_x4(al[0], alo + a_off + ks * 32);
            ldsm_x4(al[1], alo + a_off + 16 * ROWB + ks * 32);
#pragma unroll
            for (int p = 0; p < 4; p++) {
                uint32_t bh[4], bl[4];
                ldsm_x4(bh, bhi + b_off + p * 16 * ROWB + ks * 32);
                ldsm_x4(bl, blo + b_off + p * 16 * ROWB + ks * 32);
#pragma unroll
                for (int mt = 0; mt < 2; mt++) {
                    mma16816(acc[mt][2 * p],     ah[mt], bh + 0);
                    mma16816(acc[mt][2 * p + 1], ah[mt], bh + 2);
                    mma16816(acc[mt][2 * p],     ah[mt], bl + 0);
                    mma16816(acc[mt][2 * p + 1], ah[mt], bl + 2);
                    mma16816(acc[mt][2 * p],     al[mt], bh + 0);
                    mma16816(acc[mt][2 * p + 1], al[mt], bh + 2);
                }
            }
        }
    };

    ldgA(0);
    loadB(0, 0); cp_commit();
    if (niter > 1) loadB(1, 1);
    cp_commit();
    if (niter > 2) loadB(2, 2);
    cp_commit();
    stsA(0);

    for (int it = 0; it < niter; it++) {
        cp_wait<2>();
        __syncthreads();
        if (it + 3 < niter) loadB((it + 3) & 3, it + 3);
        cp_commit();
        if (it + 1 < niter) ldgA(it + 1);
        compute(it & 3, it & 1);
        if (it + 1 < niter) stsA((it + 1) & 1);
        __syncthreads();
    }

    // epilogue 1: s partials from fp32 acc
    {
        float a1v[16], a2v[16];
#pragma unroll
        for (int nt = 0; nt < 8; nt++)
#pragma unroll
            for (int e = 0; e < 2; e++) {
                const int col = colBase + warpN * 64 + nt * 8 + (lane & 3) * 2 + e;
                a1v[nt * 2 + e] = a_vec[col];
                a2v[nt * 2 + e] = a_vec[OUTF + col];
            }
        const int g = (blockIdx.y << 1) | warpN;
#pragma unroll
        for (int mt = 0; mt < 2; mt++)
#pragma unroll
            for (int half = 0; half < 2; half++) {
                float p1 = 0.0f, p2 = 0.0f;
#pragma unroll
                for (int nt = 0; nt < 8; nt++)
#pragma unroll
                    for (int e = 0; e < 2; e++) {
                        const float v = acc[mt][nt][half * 2 + e];
                        p1 += v * a1v[nt * 2 + e];
                        p2 += v * a2v[nt * 2 + e];
                    }
                p1 += __shfl_xor_sync(0xffffffffu, p1, 1);
                p1 += __shfl_xor_sync(0xffffffffu, p1, 2);
                p2 += __shfl_xor_sync(0xffffffffu, p2, 1);
                p2 += __shfl_xor_sync(0xffffffffu, p2, 2);
                if ((lane & 3) == 0) {
                    const int row = mBase + warpM * 32 + mt * 16 + (lane >> 2) + half * 8;
                    spart[g * M + row] = p1;
                    spart[(g + 4) * M + row] = p2;
                }
            }
    }

    // epilogue 2: WhT fp16 transposed via smem
    {
        __half* sT = (__half*)dsm;
        __syncthreads();
#pragma unroll
        for (int mt = 0; mt < 2; mt++)
#pragma unroll
            for (int nt = 0; nt < 8; nt++)
#pragma unroll
                for (int q = 0; q < 4; q++) {
                    const int nl = warpN * 64 + nt * 8 + (lane & 3) * 2 + (q & 1);
                    const int ml = warpM * 32 + mt * 16 + (lane >> 2) + (q >> 1) * 8;
                    sT[nl * 136 + ml] = __float2half_rn(acc[mt][nt][q]);
                }
        __syncthreads();
#pragma unroll
        for (int t = 0; t < 8; t++) {
            const int c = tid + t * 256;
            const int n = c >> 4;
            const int m8 = (c & 15) * 8;
            uint4 v = *(const uint4*)&sT[n * 136 + m8];
            *(uint4*)&WhT[(size_t)(colBase + n) * M + mBase + m8] = v;
        }
    }
}

// ---------------- combine s partials ----------------
__global__ void combine_s(const float* __restrict__ spart, float* __restrict__ ssrc,
                          float* __restrict__ sdst, int M) {
    int i = blockIdx.x * blockDim.x + threadIdx.x;
    if (i >= M) return;
    ssrc[i] = spart[0 * M + i] + spart[1 * M + i] + spart[2 * M + i] + spart[3 * M + i];
    sdst[i] = spart[4 * M + i] + spart[5 * M + i] + spart[6 * M + i] + spart[7 * M + i];
}

// ==================== GEMM-2 (R15 exact): alternating balanced attention store ====================
// A = attention fp16, B = WhT fp16, 8-stage cp.async, single product, 128 CTAs.
// Every CTA stores the fp32 attention for its A tile on iterations where
// (it & 1) == blockIdx.y; store trails compute (R15 ordering — load-bearing).
#define G2_NSTAGE 8
#define G2_DSMEM  (G2_NSTAGE * 2 * TILEB)        // 163840

__global__ __launch_bounds__(256, 1)
void mma_gemm2(const __half* __restrict__ Ah, const __half* __restrict__ Bh,
               float* __restrict__ attn, float* __restrict__ C, int K, int niter) {
    extern __shared__ __align__(128) char dsm[];
    const uint32_t sb = smem_u32(dsm);

    const int tid   = threadIdx.x;
    const int wid   = tid >> 5;
    const int lane  = tid & 31;
    const int warpM = wid & 3;
    const int warpN = wid >> 2;
    const int mBase = blockIdx.x * 128;
    const int colBase = blockIdx.y * 128;
    const int storePar = blockIdx.y & 1;

    float acc[2][8][4];
#pragma unroll
    for (int mt = 0; mt < 2; mt++)
#pragma unroll
        for (int nt = 0; nt < 8; nt++)
#pragma unroll
            for (int q = 0; q < 4; q++) acc[mt][nt][q] = 0.0f;

    auto loadStage = [&](int s, int it) {
        const uint32_t st = sb + s * (2 * TILEB);
#pragma unroll
        for (int t = 0; t < 4; t++) {
            const int c = tid + t * 256;
            const int tile = c >> 9;              // 0:A 1:B
            const int r = (c >> 2) & 127;
            const int seg = c & 3;
            const __half* base = tile ? Bh : Ah;
            const int rowg = tile ? (colBase + r) : (mBase + r);
            cp16(st + tile * TILEB + r * ROWB + seg * 16,
                 base + (size_t)rowg * K + it * 32 + seg * 8);
        }
    };

    // fp32 attention store from the resident A fp16 tile (stage s = K-chunk it)
    auto storeAttn = [&](int s, int it) {
        const uint32_t ast = sb + s * (2 * TILEB);
#pragma unroll
        for (int t = 0; t < 2; t++) {
            const int c = tid + t * 256;          // 512 chunks of 8 halfs
            const int r = c >> 2;
            const int seg = c & 3;
            uint32_t u[4];
            lds_v4(ast + r * ROWB + seg * 16, u);
            float* dst = attn + (size_t)(mBase + r) * K + it * 32 + seg * 8;
            float2 f0 = __half22float2(*(__half2*)&u[0]);
            float2 f1 = __half22float2(*(__half2*)&u[1]);
            float2 f2 = __half22float2(*(__half2*)&u[2]);
            float2 f3 = __half22float2(*(__half2*)&u[3]);
            *(float4*)dst       = make_float4(f0.x, f0.y, f1.x, f1.y);
            *(float4*)(dst + 4) = make_float4(f2.x, f2.y, f3.x, f3.y);
        }
    };

    const uint32_t a_off = (uint32_t)(warpM * 32 + (lane & 15)) * ROWB + (lane >> 4) * 16;
    const uint32_t b_off = (uint32_t)(warpN * 64 + ((lane >> 4) & 1) * 8 + (lane & 7)) * ROWB
                         + ((lane >> 3) & 1) * 16;

    auto compute = [&](int s) {
        const uint32_t ahi = sb + s * (2 * TILEB);
        const uint32_t bhi = ahi + TILEB;
#pragma unroll
        for (int ks = 0; ks < 2; ks++) {
            uint32_t ah[2][4];
            ldsm_x4(ah[0], ahi + a_off + ks * 32);
            ldsm_x4(ah[1], ahi + a_off + 16 * ROWB + ks * 32);
#pragma unroll
            for (int p = 0; p < 4; p++) {
                uint32_t bh[4];
                ldsm_x4(bh, bhi + b_off + p * 16 * ROWB + ks * 32);
#pragma unroll
                for (int mt = 0; mt < 2; mt++) {
                    mma16816(acc[mt][2 * p],     ah[mt], bh + 0);
                    mma16816(acc[mt][2 * p + 1], ah[mt], bh + 2);
                }
            }
        }
    };

#pragma unroll
    for (int s = 0; s < G2_NSTAGE - 1; s++) {
        if (s < niter) loadStage(s, s);
        cp_commit();
    }
    for (int it = 0; it < niter; it++) {
        cp_wait<G2_NSTAGE - 2>();
        __syncthreads();
        if (it + G2_NSTAGE - 1 < niter)
            loadStage((it + G2_NSTAGE - 1) & (G2_NSTAGE - 1), it + G2_NSTAGE - 1);
        cp_commit();
        compute(it & (G2_NSTAGE - 1));
        if ((it & 1) == storePar) storeAttn(it & (G2_NSTAGE - 1), it);
    }

#pragma unroll
    for (int mt = 0; mt < 2; mt++) {
        const int r0 = mBase + warpM * 32 + mt * 16 + (lane >> 2);
#pragma unroll
        for (int nt = 0; nt < 8; nt++) {
            const int col = colBase + warpN * 64 + nt * 8 + (lane & 3) * 2;
            *(float2*)(C + (size_t)r0 * 256 + col) = make_float2(acc[mt][nt][0], acc[mt][nt][1]);
            *(float2*)(C + (size_t)(r0 + 8) * 256 + col) = make_float2(acc[mt][nt][2], acc[mt][nt][3]);
        }
    }
}

// ---------------- prep: W fp32 -> fp16 hi/lo ----------------
__global__ void prep_split(const float* __restrict__ X, __half* __restrict__ hi,
                           __half* __restrict__ lo, int n4) {
    int i = blockIdx.x * blockDim.x + threadIdx.x;
    if (i >= n4) return;
    float4 v = ((const float4*)X)[i];
    __half h0 = __float2half_rn(v.x), h1 = __float2half_rn(v.y);
    __half h2 = __float2half_rn(v.z), h3 = __float2half_rn(v.w);
    __half l0 = __float2half_rn(v.x - __half2float(h0));
    __half l1 = __float2half_rn(v.y - __half2float(h1));
    __half l2 = __float2half_rn(v.z - __half2float(h2));
    __half l3 = __float2half_rn(v.w - __half2float(h3));
    ((uint2*)hi)[i] = make_uint2(
        (uint32_t)__half_as_ushort(h0) | ((uint32_t)__half_as_ushort(h1) << 16),
        (uint32_t)__half_as_ushort(h2) | ((uint32_t)__half_as_ushort(h3) << 16));
    ((uint2*)lo)[i] = make_uint2(
        (uint32_t)__half_as_ushort(l0) | ((uint32_t)__half_as_ushort(l1) << 16),
        (uint32_t)__half_as_ushort(l2) | ((uint32_t)__half_as_ushort(l3) << 16));
}

// ---------------- masked row softmax (2-pass, fp16 output only) ----------------
// __launch_bounds__(512, 4): cap at 32 regs -> 4 blocks/SM (was reg-limited to 3).
__global__ __launch_bounds__(512, 4)
void attn_softmax(const float* __restrict__ adj, const float* __restrict__ sdst,
                  const float* __restrict__ ssrc, __half* __restrict__ atth, int Nn) {
    extern __shared__ float sh[];
    float* red = sh + Nn;
    const int i = blockIdx.x;
    const int tid = threadIdx.x;
    const int T = blockDim.x;
    const int n4 = Nn >> 2;

    const float4* adj4 = (const float4*)(adj + (size_t)i * Nn);
    const float4* sd4 = (const float4*)sdst;
    float4* sh4 = (float4*)sh;
    const float si = ssrc[i];

    float sum = 0.0f;
    for (int v = tid; v < n4; v += T) {
        float4 a = adj4[v];
        float4 s = sd4[v];
        float4 p;
        float x;
        x = si + s.x; x = (x > 0.0f) ? x : ALPHA * x;
        p.x = (a.x > 0.0f) ? __expf(x) : 0.0f;
        x = si + s.y; x = (x > 0.0f) ? x : ALPHA * x;
        p.y = (a.y > 0.0f) ? __expf(x) : 0.0f;
        x = si + s.z; x = (x > 0.0f) ? x : ALPHA * x;
        p.z = (a.z > 0.0f) ? __expf(x) : 0.0f;
        x = si + s.w; x = (x > 0.0f) ? x : ALPHA * x;
        p.w = (a.w > 0.0f) ? __expf(x) : 0.0f;
        sum += p.x + p.y + p.z + p.w;
        sh4[v] = p;
    }
#pragma unroll
    for (int off = 16; off > 0; off >>= 1)
        sum += __shfl_down_sync(0xffffffffu, sum, off);
    if ((tid & 31) == 0) red[tid >> 5] = sum;
    __syncthreads();
    if (tid == 0) {
        float ss = 0.0f;
        int nw = T >> 5;
        for (int w = 0; w < nw; w++) ss += red[w];
        red[32] = ss;
    }
    __syncthreads();
    const float total = red[32];

    uint2* h2 = (uint2*)(atth + (size_t)i * Nn);
    const bool empty = (total == 0.0f);
    const float inv = empty ? (1.0f / (float)Nn) : (1.0f / total);

    for (int v = tid; v < n4; v += T) {
        float4 p;
        if (empty) {
            p = make_float4(inv, inv, inv, inv);  // softmax over all -9e15 = uniform
        } else {
            p = sh4[v];
            p.x *= inv; p.y *= inv; p.z *= inv; p.w *= inv;
        }
        __half q0 = __float2half_rn(p.x), q1 = __float2half_rn(p.y);
        __half q2 = __float2half_rn(p.z), q3 = __float2half_rn(p.w);
        h2[v] = make_uint2(
            (uint32_t)__half_as_ushort(q0) | ((uint32_t)__half_as_ushort(q1) << 16),
            (uint32_t)__half_as_ushort(q2) | ((uint32_t)__half_as_ushort(q3) << 16));
    }
}

// ---------------- launcher ----------------
extern "C" void kernel_launch(void* const* d_in, const int* in_sizes, int n_in,
                              void* d_out, int out_size) {
    const float* h     = (const float*)d_in[0];   // [N, IN_F]
    const float* adj   = (const float*)d_in[1];   // [N, N]
    const float* W     = (const float*)d_in[2];   // [OUT_F, IN_F]
    const float* a_vec = (const float*)d_in[3];   // [2*OUT_F]

    int OUTF = in_sizes[3] / 2;                   // 256
    int INF  = in_sizes[2] / OUTF;                // 512
    int N    = in_sizes[0] / INF;                 // 8192

    float *spart, *ssrc, *sdst, *attn_fb;
    __half *Whi, *Wlo, *WhT, *atth;
    cudaGetSymbolAddress((void**)&Whi,     g_Whi);
    cudaGetSymbolAddress((void**)&Wlo,     g_Wlo);
    cudaGetSymbolAddress((void**)&WhT,     g_WhT);
    cudaGetSymbolAddress((void**)&atth,    g_attn_h);
    cudaGetSymbolAddress((void**)&spart,   g_spart);
    cudaGetSymbolAddress((void**)&ssrc,    g_ssrc);
    cudaGetSymbolAddress((void**)&sdst,    g_sdst);
    cudaGetSymbolAddress((void**)&attn_fb, g_attn_fb);

    float* h_prime = (float*)d_out;
    long long need = (long long)N * OUTF + (long long)N * N;
    float* attn = ((long long)out_size >= need) ? (h_prime + (size_t)N * OUTF) : attn_fb;

    cudaFuncSetAttribute(gemm1_fused, cudaFuncAttributeMaxDynamicSharedMemorySize, G1_DSMEM);
    cudaFuncSetAttribute(mma_gemm2,   cudaFuncAttributeMaxDynamicSharedMemorySize, G2_DSMEM);

    // 1) W -> fp16 hi/lo
    prep_split<<<(OUTF * INF / 4 + 255) / 256, 256>>>(W, Whi, Wlo, OUTF * INF / 4);

    // 2) fused GEMM-1: WhT fp16 + s partials
    gemm1_fused<<<dim3(N / 128, OUTF / 128), 256, G1_DSMEM>>>(
        h, Whi, Wlo, WhT, spart, a_vec, INF, INF / 32, N, OUTF);

    // 3) combine s partials
    combine_s<<<(N + 255) / 256, 256>>>(spart, ssrc, sdst, N);

    // 4) masked softmax -> fp16 attention plane only
    size_t shBytes = (size_t)N * sizeof(float) + 64 * sizeof(float);
    attn_softmax<<<N, 512, shBytes>>>(adj, sdst, ssrc, atth, N);

    // 5) GEMM-2 (R15 exact) + alternating fp32 attention store
    mma_gemm2<<<dim3(N / 128, OUTF / 128), 256, G2_DSMEM>>>(atth, WhT, attn, h_prime, N, N / 32);
}